// round 7
// baseline (speedup 1.0000x reference)
#include <cuda_runtime.h>
#include <math.h>

#define Bv 8
#define Tv 4096
#define Dv 1024
#define EPS 0.01f
#define TT 64                  // timesteps per block
#define TILES (Tv / TT)        // 64
#define LOG2_C (-0.014499569695115089f)   // log2(0.99)
#define LN_C   (-0.010050335853501441)    // ln(0.99), double

// Device scratch — 16B-aligned (accessed through float4 casts)
__device__ __align__(16) float d_y[Bv * Tv];                       // x_t . w
__device__ __align__(16) float d_mempart[(size_t)Bv * TILES * Dv]; // per-tile partials
__device__ __align__(16) int   d_tilecnt[Bv * TILES];              // gates per tile
__device__ int d_count[Bv];   // arrival counters; zero at load, reset by last block

// ---------------------------------------------------------------------------
// Fused kernel: streaming pass over write_signal (128 MB), then the block
// that finishes LAST within its batch performs that batch's epilogue
// (affine scalar scan -> bias, decay-scaled memory reduction) in-kernel.
// grid = (TILES, Bv), 256 threads (8 warps). Deterministic.
// ---------------------------------------------------------------------------
__global__ void __launch_bounds__(256, 2) fused_kernel(const float* __restrict__ x,
                                                       const float* __restrict__ w,
                                                       const int* __restrict__ pad,
                                                       const int* __restrict__ upd,
                                                       float* __restrict__ out) {
    const int b = blockIdx.y;
    const int t0 = blockIdx.x * TT;
    const int tid = threadIdx.x;
    const int warp = tid >> 5;
    const int lane = tid & 31;

    // smem is float4-cast: MUST be 16B-aligned (round-4/5 trap root cause).
    __shared__ __align__(16) float smem[Dv];
    __shared__ __align__(16) float s_coef[TT];
    __shared__ unsigned s_mask[2];
    __shared__ bool s_last;

    // ---- tile-local coefficients from gate bits -------------------------
    if (tid < 64) {
        int t = t0 + tid;
        bool g = (pad[b * Tv + t] == 0) && (upd[b * Tv + t] != 0);
        unsigned bal = __ballot_sync(0xffffffffu, g);
        if ((tid & 31) == 0) s_mask[tid >> 5] = bal;
    }
    __syncthreads();
    if (tid < 64) {
        unsigned m0 = s_mask[0], m1 = s_mask[1];
        int lt = tid & 31;
        bool g; int cnt;
        if (tid < 32) {
            g = (m0 >> lt) & 1u;
            unsigned hi = (lt == 31) ? 0u : (m0 >> (lt + 1));
            cnt = __popc(hi) + __popc(m1);
        } else {
            g = (m1 >> lt) & 1u;
            unsigned hi = (lt == 31) ? 0u : (m1 >> (lt + 1));
            cnt = __popc(hi);
        }
        s_coef[tid] = g ? (EPS * exp2f((float)cnt * LOG2_C)) : 0.0f;
        if (tid == 0) d_tilecnt[b * TILES + blockIdx.x] = __popc(m0) + __popc(m1);
    }
    __syncthreads();

    // ---- main streaming loop: GEMV + tile-weighted accumulate -----------
    float4 wv[8];
#pragma unroll
    for (int j = 0; j < 8; j++) wv[j] = __ldg(&((const float4*)w)[j * 32 + lane]);

    float4 macc[8];
#pragma unroll
    for (int j = 0; j < 8; j++) macc[j] = make_float4(0.f, 0.f, 0.f, 0.f);

    for (int r = warp; r < TT; r += 8) {
        const int t = t0 + r;
        const float4* row = (const float4*)(x + ((size_t)(b * Tv + t)) * Dv);
        const float c = s_coef[r];
        float dot = 0.f;
        if (c != 0.0f) {   // warp-uniform
#pragma unroll
            for (int j = 0; j < 8; j++) {
                float4 v = __ldcs(&row[j * 32 + lane]);
                dot += v.x * wv[j].x + v.y * wv[j].y + v.z * wv[j].z + v.w * wv[j].w;
                macc[j].x += c * v.x;
                macc[j].y += c * v.y;
                macc[j].z += c * v.z;
                macc[j].w += c * v.w;
            }
        } else {
#pragma unroll
            for (int j = 0; j < 8; j++) {
                float4 v = __ldcs(&row[j * 32 + lane]);
                dot += v.x * wv[j].x + v.y * wv[j].y + v.z * wv[j].z + v.w * wv[j].w;
            }
        }
#pragma unroll
        for (int off = 16; off; off >>= 1)
            dot += __shfl_down_sync(0xffffffffu, dot, off);
        if (lane == 0) d_y[b * Tv + t] = dot;
    }

    // combine 8 warps' memory partials deterministically via shared memory
    for (int wsel = 0; wsel < 8; wsel++) {
        if (warp == wsel) {
#pragma unroll
            for (int j = 0; j < 8; j++) {
                int d = j * 128 + lane * 4;
                if (wsel == 0) {
                    smem[d + 0] = macc[j].x; smem[d + 1] = macc[j].y;
                    smem[d + 2] = macc[j].z; smem[d + 3] = macc[j].w;
                } else {
                    smem[d + 0] += macc[j].x; smem[d + 1] += macc[j].y;
                    smem[d + 2] += macc[j].z; smem[d + 3] += macc[j].w;
                }
            }
        }
        __syncthreads();
    }
    {
        float4* dst = (float4*)&d_mempart[((size_t)b * TILES + blockIdx.x) * Dv];
        const float4* s4 = (const float4*)smem;
        dst[tid] = s4[tid];
    }

    // ---- last-block-done fence for this batch ---------------------------
    __threadfence();
    if (tid == 0) {
        int old = atomicAdd(&d_count[b], 1);
        s_last = (old == TILES - 1);
        if (s_last) atomicExch(&d_count[b], 0);   // reset for next graph replay
    }
    __syncthreads();
    if (!s_last) return;
    __threadfence();   // acquire: make all tiles' d_y/d_mempart/d_tilecnt visible

    // =====================================================================
    // EPILOGUE for batch b (runs in exactly one block per batch)
    // =====================================================================

    // ---- (1) affine scalar scan -> bias output --------------------------
    {
        __shared__ float sWA[8], sWC[8], sWAe[8];

        unsigned gmask = 0, pmask = 0;
        float yv[16];
        const int4* p4 = (const int4*)(pad + b * Tv);
        const int4* u4 = (const int4*)(upd + b * Tv);
#pragma unroll
        for (int q = 0; q < 4; q++) {
            int4 a = __ldg(&p4[tid * 4 + q]);
            int4 c = __ldg(&u4[tid * 4 + q]);
            int pa[4] = {a.x, a.y, a.z, a.w};
            int ua[4] = {c.x, c.y, c.z, c.w};
            float4 yq = *((const float4*)&d_y[b * Tv + tid * 16 + q * 4]);
            float ya[4] = {yq.x, yq.y, yq.z, yq.w};
#pragma unroll
            for (int r = 0; r < 4; r++) {
                int k = q * 4 + r;
                if (pa[r] != 0) pmask |= (1u << k);
                if (pa[r] == 0 && ua[r] != 0) gmask |= (1u << k);
                yv[k] = ya[r];
            }
        }

        // compose affine transform over my 16 elems: u_out = C*u_in + A
        float C = 1.f, A = 0.f;
#pragma unroll
        for (int k = 0; k < 16; k++) {
            if ((gmask >> k) & 1u) { A = 0.99f * A + 0.01f * yv[k]; C *= 0.99f; }
        }

        // warp inclusive scan of affine composition
#pragma unroll
        for (int off = 1; off < 32; off <<= 1) {
            float pC = __shfl_up_sync(0xffffffffu, C, off);
            float pA = __shfl_up_sync(0xffffffffu, A, off);
            float nA = fmaf(C, pA, A);
            float nC = C * pC;
            if (lane >= off) { A = nA; C = nC; }
        }
        float eC = __shfl_up_sync(0xffffffffu, C, 1);
        float eA = __shfl_up_sync(0xffffffffu, A, 1);
        if (lane == 0) { eC = 1.f; eA = 0.f; }
        if (lane == 31) { sWC[warp] = C; sWA[warp] = A; }
        __syncthreads();
        if (tid == 0) {
            float c = 1.f, a = 0.f;
#pragma unroll
            for (int ww = 0; ww < 8; ww++) {
                sWAe[ww] = a;
                float na = fmaf(sWC[ww], a, sWA[ww]);
                c = sWC[ww] * c; a = na;
            }
        }
        __syncthreads();

        float u = fmaf(eC, sWAe[warp], eA);

        float4* o4 = (float4*)(out + b * Tv + tid * 16);
#pragma unroll
        for (int q = 0; q < 4; q++) {
            float ob[4];
#pragma unroll
            for (int r = 0; r < 4; r++) {
                int k = q * 4 + r;
                if ((gmask >> k) & 1u) u = fmaf(0.99f, u, 0.01f * yv[k]);
                if ((pmask >> k) & 1u) {
                    ob[r] = 1.0f;
                } else {
                    float bb = 1.0f + tanhf(u);
                    ob[r] = fminf(fmaxf(bb, 0.8f), 1.2f);
                }
            }
            o4[q] = make_float4(ob[0], ob[1], ob[2], ob[3]);
        }
        __syncthreads();
    }

    // ---- (2) memory reduction with per-tile decay scales -----------------
    {
        __shared__ int s_cnt[TILES];
        __shared__ float s_scale[TILES];
        if (tid < TILES) s_cnt[tid] = d_tilecnt[b * TILES + tid];
        __syncthreads();
        if (tid < TILES) {
            int after = 0;
            for (int j = tid + 1; j < TILES; j++) after += s_cnt[j];
            s_scale[tid] = (float)exp((double)after * LN_C);
        }
        __syncthreads();

        // 256 threads, each owns one float4 of the (Dv) output for batch b
        const float4* mp4 = (const float4*)&d_mempart[(size_t)b * TILES * Dv];
        float4 s = make_float4(0.f, 0.f, 0.f, 0.f);
#pragma unroll 8
        for (int tile = 0; tile < TILES; tile++) {
            float sc = s_scale[tile];
            float4 v = mp4[(size_t)tile * 256 + tid];
            s.x = fmaf(sc, v.x, s.x); s.y = fmaf(sc, v.y, s.y);
            s.z = fmaf(sc, v.z, s.z); s.w = fmaf(sc, v.w, s.w);
        }
        ((float4*)(out + Bv * Tv + b * Dv))[tid] = s;
    }
}

// ---------------------------------------------------------------------------
extern "C" void kernel_launch(void* const* d_in, const int* in_sizes, int n_in,
                              void* d_out, int out_size) {
    const float* x = (const float*)d_in[0];            // write_signal (8,4096,1024)
    const int* pad = (const int*)d_in[1];              // pad_mask bool -> int32 (8,4096)
    const int* upd = (const int*)d_in[2];              // update_mask bool -> int32 (8,4096)
    const float* w = (const float*)d_in[3];            // w (1024,)
    float* out = (float*)d_out;                        // [bias (8*4096) | memory (8*1024)]

    dim3 grid(TILES, Bv);
    fused_kernel<<<grid, 256>>>(x, w, pad, upd, out);
}

// round 8
// speedup vs baseline: 1.0806x; 1.0806x over previous
#include <cuda_runtime.h>
#include <math.h>

#define Bv 8
#define Tv 4096
#define Dv 1024
#define EPS 0.01f
#define TT 64                  // timesteps per block
#define TILES (Tv / TT)        // 64
#define LOG2_C (-0.014499569695115089f)   // log2(0.99)
#define LN_C   (-0.010050335853501441)    // ln(0.99), double

// Device scratch — 16B-aligned (accessed through float4 casts)
__device__ __align__(16) float d_y[Bv * Tv];                       // x_t . w
__device__ __align__(16) float d_mempart[(size_t)Bv * TILES * Dv]; // per-tile partials
__device__ __align__(16) int   d_tilecnt[Bv * TILES];              // gates per tile

// ---------------------------------------------------------------------------
// Main pass: warp-slice layout. Each warp owns a 128-float D-slice; each lane
// owns one float4 (d4 = warp*32+lane). All warps walk all 64 rows.
//   - y partials: per-warp 5-shfl reduce -> s_pdot[row][warp]; 64 threads
//     finish the 8-way sums in fixed order (deterministic).
//   - macc: 1 float4/lane, written straight to d_mempart (no combine loop).
// Low regs -> >=3 blocks/SM -> enough loads in flight to cover DRAM latency.
// ---------------------------------------------------------------------------
__global__ void __launch_bounds__(256, 3) main_kernel(const float* __restrict__ x,
                                                      const float* __restrict__ w,
                                                      const int* __restrict__ pad,
                                                      const int* __restrict__ upd) {
    const int b = blockIdx.y;
    const int t0 = blockIdx.x * TT;
    const int tid = threadIdx.x;
    const int warp = tid >> 5;
    const int lane = tid & 31;

    __shared__ __align__(16) float s_coef[TT];
    __shared__ float s_pdot[TT * 8];     // [row][warp]
    __shared__ unsigned s_mask[2];

    // ---- tile-local coefficients from gate bits -------------------------
    if (tid < 64) {
        int t = t0 + tid;
        bool g = (pad[b * Tv + t] == 0) && (upd[b * Tv + t] != 0);
        unsigned bal = __ballot_sync(0xffffffffu, g);
        if ((tid & 31) == 0) s_mask[tid >> 5] = bal;
    }
    __syncthreads();
    if (tid < 64) {
        unsigned m0 = s_mask[0], m1 = s_mask[1];
        int lt = tid & 31;
        bool g; int cnt;
        if (tid < 32) {
            g = (m0 >> lt) & 1u;
            unsigned hi = (lt == 31) ? 0u : (m0 >> (lt + 1));
            cnt = __popc(hi) + __popc(m1);
        } else {
            g = (m1 >> lt) & 1u;
            unsigned hi = (lt == 31) ? 0u : (m1 >> (lt + 1));
            cnt = __popc(hi);
        }
        s_coef[tid] = g ? (EPS * exp2f((float)cnt * LOG2_C)) : 0.0f;
        if (tid == 0) d_tilecnt[b * TILES + blockIdx.x] = __popc(m0) + __popc(m1);
    }
    __syncthreads();

    // ---- streaming loop ---------------------------------------------------
    const int d4 = warp * 32 + lane;                 // float4 index in D (0..255)
    const float4 wv = __ldg(&((const float4*)w)[d4]);
    float4 macc = make_float4(0.f, 0.f, 0.f, 0.f);
    const float4* xb = (const float4*)(x + ((size_t)(b * Tv + t0)) * Dv);

#pragma unroll 8
    for (int r = 0; r < TT; r++) {
        float4 v = __ldcs(&xb[r * 256 + d4]);        // 512B contiguous per warp
        const float c = s_coef[r];
        float dot = v.x * wv.x + v.y * wv.y + v.z * wv.z + v.w * wv.w;
        if (c != 0.0f) {                             // warp-uniform (scalar per row)
            macc.x = fmaf(c, v.x, macc.x);
            macc.y = fmaf(c, v.y, macc.y);
            macc.z = fmaf(c, v.z, macc.z);
            macc.w = fmaf(c, v.w, macc.w);
        }
#pragma unroll
        for (int off = 16; off; off >>= 1)
            dot += __shfl_down_sync(0xffffffffu, dot, off);
        if (lane == 0) s_pdot[r * 8 + warp] = dot;
    }
    __syncthreads();

    // finish dots: 64 threads, fixed-order 8-way sums (deterministic)
    if (tid < TT) {
        float s = 0.f;
#pragma unroll
        for (int ww = 0; ww < 8; ww++) s += s_pdot[tid * 8 + ww];
        d_y[b * Tv + t0 + tid] = s;
    }

    // direct per-tile partial write (each thread owns its float4 of D)
    ((float4*)&d_mempart[((size_t)b * TILES + blockIdx.x) * Dv])[d4] = macc;
}

// ---------------------------------------------------------------------------
// Epilogue (fused): blocks 0..7  -> per-batch affine scan (float, shuffles)
//                   blocks 8..71 -> memory reduction with per-tile decay scale
// ---------------------------------------------------------------------------
__global__ void __launch_bounds__(256) epilogue_kernel(const int* __restrict__ pad,
                                                       const int* __restrict__ upd,
                                                       float* __restrict__ out) {
    const int tid = threadIdx.x;
    if (blockIdx.x < Bv) {
        // ---------------- scan: u_t = c_t*u_{t-1} + eps*g_t*y_t ----------
        const int b = blockIdx.x;
        const int warp = tid >> 5;
        const int lane = tid & 31;
        __shared__ float sWA[8];      // warp aggregate A
        __shared__ float sWC[8];      // warp aggregate C
        __shared__ float sWAe[8];     // warp exclusive prefix A

        // load 16 timesteps per thread
        bool gv[16]; bool pvb[16]; float yv[16];
        const int4* p4 = (const int4*)(pad + b * Tv);
        const int4* u4 = (const int4*)(upd + b * Tv);
#pragma unroll
        for (int q = 0; q < 4; q++) {
            int4 a = __ldg(&p4[tid * 4 + q]);
            int4 c = __ldg(&u4[tid * 4 + q]);
            int pa[4] = {a.x, a.y, a.z, a.w};
            int ua[4] = {c.x, c.y, c.z, c.w};
            float4 yq = *((const float4*)&d_y[b * Tv + tid * 16 + q * 4]);
            float ya[4] = {yq.x, yq.y, yq.z, yq.w};
#pragma unroll
            for (int r = 0; r < 4; r++) {
                pvb[q * 4 + r] = (pa[r] != 0);
                gv[q * 4 + r] = (pa[r] == 0) && (ua[r] != 0);
                yv[q * 4 + r] = ya[r];
            }
        }

        // compose affine transform over my 16 elems: u_out = C*u_in + A
        float C = 1.f, A = 0.f;
#pragma unroll
        for (int k = 0; k < 16; k++) {
            if (gv[k]) { A = 0.99f * A + 0.01f * yv[k]; C *= 0.99f; }
        }

        // warp inclusive scan of affine composition
#pragma unroll
        for (int off = 1; off < 32; off <<= 1) {
            float pC = __shfl_up_sync(0xffffffffu, C, off);
            float pA = __shfl_up_sync(0xffffffffu, A, off);
            float nA = fmaf(C, pA, A);
            float nC = C * pC;
            if (lane >= off) { A = nA; C = nC; }
        }
        // thread-exclusive within warp
        float eC = __shfl_up_sync(0xffffffffu, C, 1);
        float eA = __shfl_up_sync(0xffffffffu, A, 1);
        if (lane == 0) { eC = 1.f; eA = 0.f; }
        if (lane == 31) { sWC[warp] = C; sWA[warp] = A; }
        __syncthreads();
        if (tid == 0) {
            float c = 1.f, a = 0.f;
#pragma unroll
            for (int ww = 0; ww < 8; ww++) {
                sWAe[ww] = a;
                float na = fmaf(sWC[ww], a, sWA[ww]);
                c = sWC[ww] * c; a = na;
            }
        }
        __syncthreads();

        // u at start of my 16 elems (u0 = 0)
        float u = fmaf(eC, sWAe[warp], eA);

        float ob[16];
#pragma unroll
        for (int k = 0; k < 16; k++) {
            if (gv[k]) u = fmaf(0.99f, u, 0.01f * yv[k]);
            float bias;
            if (pvb[k]) {
                bias = 1.0f;
            } else {
                bias = 1.0f + tanhf(u);
                bias = fminf(fmaxf(bias, 0.8f), 1.2f);
            }
            ob[k] = bias;
        }
        float4* o4 = (float4*)(out + b * Tv + tid * 16);
#pragma unroll
        for (int q = 0; q < 4; q++)
            o4[q] = make_float4(ob[q * 4], ob[q * 4 + 1], ob[q * 4 + 2], ob[q * 4 + 3]);
    } else {
        // ---------------- memred: memory[b,d] = sum_tiles scale_tile*partial ---
        const int m = blockIdx.x - Bv;          // 0..63
        const int oi = tid >> 3;                // 0..31
        const int sub = tid & 7;                // 0..7
        const int o4 = m * 32 + oi;             // float4 index over B*D
        const int b = o4 >> 8;                  // 256 float4 per batch (constant per block)
        const int d4 = o4 & 255;

        __shared__ int s_cnt[TILES];
        __shared__ float s_scale[TILES];
        if (tid < TILES) s_cnt[tid] = d_tilecnt[b * TILES + tid];
        __syncthreads();
        if (tid < TILES) {
            int after = 0;
            for (int j = tid + 1; j < TILES; j++) after += s_cnt[j];
            s_scale[tid] = (float)exp((double)after * LN_C);
        }
        __syncthreads();

        const float4* mp4 = (const float4*)d_mempart;
        float4 s = make_float4(0.f, 0.f, 0.f, 0.f);
#pragma unroll
        for (int k = 0; k < 8; k++) {
            int tile = sub * 8 + k;
            float sc = s_scale[tile];
            float4 v = mp4[((size_t)(b * TILES + tile)) * 256 + d4];
            s.x = fmaf(sc, v.x, s.x); s.y = fmaf(sc, v.y, s.y);
            s.z = fmaf(sc, v.z, s.z); s.w = fmaf(sc, v.w, s.w);
        }
        // reduce across sub (groups of 8 lanes) -- fixed tree, deterministic
#pragma unroll
        for (int off = 4; off; off >>= 1) {
            s.x += __shfl_down_sync(0xffffffffu, s.x, off);
            s.y += __shfl_down_sync(0xffffffffu, s.y, off);
            s.z += __shfl_down_sync(0xffffffffu, s.z, off);
            s.w += __shfl_down_sync(0xffffffffu, s.w, off);
        }
        if (sub == 0)
            ((float4*)(out + Bv * Tv))[o4] = s;
    }
}

// ---------------------------------------------------------------------------
extern "C" void kernel_launch(void* const* d_in, const int* in_sizes, int n_in,
                              void* d_out, int out_size) {
    const float* x = (const float*)d_in[0];            // write_signal (8,4096,1024)
    const int* pad = (const int*)d_in[1];              // pad_mask bool -> int32 (8,4096)
    const int* upd = (const int*)d_in[2];              // update_mask bool -> int32 (8,4096)
    const float* w = (const float*)d_in[3];            // w (1024,)
    float* out = (float*)d_out;                        // [bias (8*4096) | memory (8*1024)]

    dim3 grid(TILES, Bv);
    main_kernel<<<grid, 256>>>(x, w, pad, upd);
    epilogue_kernel<<<Bv + 64, 256>>>(pad, upd, out);
}

// round 9
// speedup vs baseline: 1.2401x; 1.1476x over previous
#include <cuda_runtime.h>
#include <math.h>

#define Bv 8
#define Tv 4096
#define Dv 1024
#define EPS 0.01f
#define TT 64                  // timesteps per block
#define TILES (Tv / TT)        // 64
#define LOG2_C (-0.014499569695115089f)   // log2(0.99)
#define LN_C   (-0.010050335853501441)    // ln(0.99), double

// Device scratch — 16B-aligned (accessed through float4 casts)
__device__ __align__(16) float d_y[Bv * Tv];                       // x_t . w
__device__ __align__(16) float d_mempart[(size_t)Bv * TILES * Dv]; // per-tile partials
__device__ __align__(16) int   d_tilecnt[Bv * TILES];              // gates per tile

// ---------------------------------------------------------------------------
// Main pass: warp-slice layout + explicit 8-deep load batching.
// Each warp owns a 128-float D-slice; each lane owns one float4.
// Inner loop: chunk of 8 rows -> 8 independent LDG.128 front-batched (MLP=8),
// then dots/macc/shfl. 4 blocks/SM (launch_bounds) -> 32 warps -> ~32KB
// in flight per SM, covering DRAM latency (~17KB needed).
// ---------------------------------------------------------------------------
__global__ void __launch_bounds__(256, 4) main_kernel(const float* __restrict__ x,
                                                      const float* __restrict__ w,
                                                      const int* __restrict__ pad,
                                                      const int* __restrict__ upd) {
    const int b = blockIdx.y;
    const int t0 = blockIdx.x * TT;
    const int tid = threadIdx.x;
    const int warp = tid >> 5;
    const int lane = tid & 31;

    __shared__ __align__(16) float s_coef[TT];
    __shared__ float s_pdot[TT * 8];     // [row][warp]
    __shared__ unsigned s_mask[2];

    // ---- tile-local coefficients from gate bits -------------------------
    if (tid < 64) {
        int t = t0 + tid;
        bool g = (pad[b * Tv + t] == 0) && (upd[b * Tv + t] != 0);
        unsigned bal = __ballot_sync(0xffffffffu, g);
        if ((tid & 31) == 0) s_mask[tid >> 5] = bal;
    }
    __syncthreads();
    if (tid < 64) {
        unsigned m0 = s_mask[0], m1 = s_mask[1];
        int lt = tid & 31;
        bool g; int cnt;
        if (tid < 32) {
            g = (m0 >> lt) & 1u;
            unsigned hi = (lt == 31) ? 0u : (m0 >> (lt + 1));
            cnt = __popc(hi) + __popc(m1);
        } else {
            g = (m1 >> lt) & 1u;
            unsigned hi = (lt == 31) ? 0u : (m1 >> (lt + 1));
            cnt = __popc(hi);
        }
        s_coef[tid] = g ? (EPS * exp2f((float)cnt * LOG2_C)) : 0.0f;
        if (tid == 0) d_tilecnt[b * TILES + blockIdx.x] = __popc(m0) + __popc(m1);
    }
    __syncthreads();

    // ---- streaming loop ---------------------------------------------------
    const int d4 = warp * 32 + lane;                 // float4 index in D (0..255)
    const float4 wv = __ldg(&((const float4*)w)[d4]);
    float4 macc = make_float4(0.f, 0.f, 0.f, 0.f);
    const float4* xb = (const float4*)(x + ((size_t)(b * Tv + t0)) * Dv) + d4;

#pragma unroll 1
    for (int rr = 0; rr < TT; rr += 8) {
        // phase 1: 8 independent loads, no consumers in between (MLP_p1 = 8)
        float4 v[8];
#pragma unroll
        for (int j = 0; j < 8; j++)
            v[j] = __ldcs(xb + (size_t)(rr + j) * 256);

        // phase 2: dots + weighted accumulate + warp reduce
#pragma unroll
        for (int j = 0; j < 8; j++) {
            const float c = s_coef[rr + j];
            float dot = v[j].x * wv.x + v[j].y * wv.y + v[j].z * wv.z + v[j].w * wv.w;
            macc.x = fmaf(c, v[j].x, macc.x);
            macc.y = fmaf(c, v[j].y, macc.y);
            macc.z = fmaf(c, v[j].z, macc.z);
            macc.w = fmaf(c, v[j].w, macc.w);
#pragma unroll
            for (int off = 16; off; off >>= 1)
                dot += __shfl_down_sync(0xffffffffu, dot, off);
            if (lane == 0) s_pdot[(rr + j) * 8 + warp] = dot;
        }
    }
    __syncthreads();

    // finish dots: 64 threads, fixed-order 8-way sums (deterministic)
    if (tid < TT) {
        float s = 0.f;
#pragma unroll
        for (int ww = 0; ww < 8; ww++) s += s_pdot[tid * 8 + ww];
        d_y[b * Tv + t0 + tid] = s;
    }

    // direct per-tile partial write (each thread owns its float4 of D)
    ((float4*)&d_mempart[((size_t)b * TILES + blockIdx.x) * Dv])[d4] = macc;
}

// ---------------------------------------------------------------------------
// Epilogue (fused): blocks 0..7  -> per-batch affine scan (float, shuffles)
//                   blocks 8..71 -> memory reduction with per-tile decay scale
// ---------------------------------------------------------------------------
__global__ void __launch_bounds__(256) epilogue_kernel(const int* __restrict__ pad,
                                                       const int* __restrict__ upd,
                                                       float* __restrict__ out) {
    const int tid = threadIdx.x;
    if (blockIdx.x < Bv) {
        // ---------------- scan: u_t = c_t*u_{t-1} + eps*g_t*y_t ----------
        const int b = blockIdx.x;
        const int warp = tid >> 5;
        const int lane = tid & 31;
        __shared__ float sWA[8];      // warp aggregate A
        __shared__ float sWC[8];      // warp aggregate C
        __shared__ float sWAe[8];     // warp exclusive prefix A

        // load 16 timesteps per thread
        bool gv[16]; bool pvb[16]; float yv[16];
        const int4* p4 = (const int4*)(pad + b * Tv);
        const int4* u4 = (const int4*)(upd + b * Tv);
#pragma unroll
        for (int q = 0; q < 4; q++) {
            int4 a = __ldg(&p4[tid * 4 + q]);
            int4 c = __ldg(&u4[tid * 4 + q]);
            int pa[4] = {a.x, a.y, a.z, a.w};
            int ua[4] = {c.x, c.y, c.z, c.w};
            float4 yq = *((const float4*)&d_y[b * Tv + tid * 16 + q * 4]);
            float ya[4] = {yq.x, yq.y, yq.z, yq.w};
#pragma unroll
            for (int r = 0; r < 4; r++) {
                pvb[q * 4 + r] = (pa[r] != 0);
                gv[q * 4 + r] = (pa[r] == 0) && (ua[r] != 0);
                yv[q * 4 + r] = ya[r];
            }
        }

        // compose affine transform over my 16 elems: u_out = C*u_in + A
        float C = 1.f, A = 0.f;
#pragma unroll
        for (int k = 0; k < 16; k++) {
            if (gv[k]) { A = 0.99f * A + 0.01f * yv[k]; C *= 0.99f; }
        }

        // warp inclusive scan of affine composition
#pragma unroll
        for (int off = 1; off < 32; off <<= 1) {
            float pC = __shfl_up_sync(0xffffffffu, C, off);
            float pA = __shfl_up_sync(0xffffffffu, A, off);
            float nA = fmaf(C, pA, A);
            float nC = C * pC;
            if (lane >= off) { A = nA; C = nC; }
        }
        // thread-exclusive within warp
        float eC = __shfl_up_sync(0xffffffffu, C, 1);
        float eA = __shfl_up_sync(0xffffffffu, A, 1);
        if (lane == 0) { eC = 1.f; eA = 0.f; }
        if (lane == 31) { sWC[warp] = C; sWA[warp] = A; }
        __syncthreads();
        if (tid == 0) {
            float c = 1.f, a = 0.f;
#pragma unroll
            for (int ww = 0; ww < 8; ww++) {
                sWAe[ww] = a;
                float na = fmaf(sWC[ww], a, sWA[ww]);
                c = sWC[ww] * c; a = na;
            }
        }
        __syncthreads();

        // u at start of my 16 elems (u0 = 0)
        float u = fmaf(eC, sWAe[warp], eA);

        float ob[16];
#pragma unroll
        for (int k = 0; k < 16; k++) {
            if (gv[k]) u = fmaf(0.99f, u, 0.01f * yv[k]);
            float bias;
            if (pvb[k]) {
                bias = 1.0f;
            } else {
                bias = 1.0f + tanhf(u);
                bias = fminf(fmaxf(bias, 0.8f), 1.2f);
            }
            ob[k] = bias;
        }
        float4* o4 = (float4*)(out + b * Tv + tid * 16);
#pragma unroll
        for (int q = 0; q < 4; q++)
            o4[q] = make_float4(ob[q * 4], ob[q * 4 + 1], ob[q * 4 + 2], ob[q * 4 + 3]);
    } else {
        // ---------------- memred: memory[b,d] = sum_tiles scale_tile*partial ---
        const int m = blockIdx.x - Bv;          // 0..63
        const int oi = tid >> 3;                // 0..31
        const int sub = tid & 7;                // 0..7
        const int o4 = m * 32 + oi;             // float4 index over B*D
        const int b = o4 >> 8;                  // 256 float4 per batch (constant per block)
        const int d4 = o4 & 255;

        __shared__ int s_cnt[TILES];
        __shared__ float s_scale[TILES];
        if (tid < TILES) s_cnt[tid] = d_tilecnt[b * TILES + tid];
        __syncthreads();
        if (tid < TILES) {
            int after = 0;
            for (int j = tid + 1; j < TILES; j++) after += s_cnt[j];
            s_scale[tid] = (float)exp((double)after * LN_C);
        }
        __syncthreads();

        const float4* mp4 = (const float4*)d_mempart;
        float4 s = make_float4(0.f, 0.f, 0.f, 0.f);
#pragma unroll
        for (int k = 0; k < 8; k++) {
            int tile = sub * 8 + k;
            float sc = s_scale[tile];
            float4 v = mp4[((size_t)(b * TILES + tile)) * 256 + d4];
            s.x = fmaf(sc, v.x, s.x); s.y = fmaf(sc, v.y, s.y);
            s.z = fmaf(sc, v.z, s.z); s.w = fmaf(sc, v.w, s.w);
        }
        // reduce across sub (groups of 8 lanes) -- fixed tree, deterministic
#pragma unroll
        for (int off = 4; off; off >>= 1) {
            s.x += __shfl_down_sync(0xffffffffu, s.x, off);
            s.y += __shfl_down_sync(0xffffffffu, s.y, off);
            s.z += __shfl_down_sync(0xffffffffu, s.z, off);
            s.w += __shfl_down_sync(0xffffffffu, s.w, off);
        }
        if (sub == 0)
            ((float4*)(out + Bv * Tv))[o4] = s;
    }
}

// ---------------------------------------------------------------------------
extern "C" void kernel_launch(void* const* d_in, const int* in_sizes, int n_in,
                              void* d_out, int out_size) {
    const float* x = (const float*)d_in[0];            // write_signal (8,4096,1024)
    const int* pad = (const int*)d_in[1];              // pad_mask bool -> int32 (8,4096)
    const int* upd = (const int*)d_in[2];              // update_mask bool -> int32 (8,4096)
    const float* w = (const float*)d_in[3];            // w (1024,)
    float* out = (float*)d_out;                        // [bias (8*4096) | memory (8*1024)]

    dim3 grid(TILES, Bv);
    main_kernel<<<grid, 256>>>(x, w, pad, upd);
    epilogue_kernel<<<Bv + 64, 256>>>(pad, upd, out);
}